// round 1
// baseline (speedup 1.0000x reference)
#include <cuda_runtime.h>

#define HH 2048
#define WW 2048
#define HWN (HH*WW)
#define RAD 10
#define SEG 64
#define THR 1e-3f
#define EPSF 1e-9f

// Scratch planes (device globals: no allocation allowed)
__device__ float g_P0[HWN];   // vertical box of mask (persists K1 -> K5)
__device__ float g_P1[HWN];   // vertical box of b, later of S1
__device__ float g_P2[HWN];   // vertical box of b*b, later of S2
__device__ double g_red[HH * 8];   // per-row-block partial reductions (8 channels)
__device__ double g_red2[HH];      // per-row-block partial loss sums
__device__ float g_v[4];           // the 4-vector v

// ---------------------------------------------------------------------------
// K1: vertical 21-tap box sums of {mask(I), b, b*b}, per-thread sliding window
// grid (WW/256, HH/SEG), block 256. Coalesced: threads = adjacent columns.
// ---------------------------------------------------------------------------
__global__ void k1_vert(const float* __restrict__ I, const float* __restrict__ B) {
    int col = blockIdx.x * 256 + threadIdx.x;
    int r0 = blockIdx.y * SEG;
    float s0 = 0.f, s1 = 0.f, s2 = 0.f;
    for (int y = r0 - RAD; y <= r0 + RAD; ++y) {
        if (y >= 0 && y < HH) {
            float iv = I[y * WW + col], bv = B[y * WW + col];
            s0 += (iv > THR) ? 1.f : 0.f;
            s1 += bv;
            s2 += bv * bv;
        }
    }
    for (int i = 0; i < SEG; ++i) {
        int y = r0 + i;
        int o = y * WW + col;
        g_P0[o] = s0; g_P1[o] = s1; g_P2[o] = s2;
        int ya = y + RAD + 1, yr = y - RAD;
        if (ya < HH) {
            float iv = I[ya * WW + col], bv = B[ya * WW + col];
            s0 += (iv > THR) ? 1.f : 0.f; s1 += bv; s2 += bv * bv;
        }
        if (yr >= 0) {
            float iv = I[yr * WW + col], bv = B[yr * WW + col];
            s0 -= (iv > THR) ? 1.f : 0.f; s1 -= bv; s2 -= bv * bv;
        }
    }
}

// ---------------------------------------------------------------------------
// Block-wide inclusive prefix sum of 2304 floats in shared memory (256 thr).
// Stride-9 per-thread segments => conflict-free (gcd(9,32)=1).
// ---------------------------------------------------------------------------
__device__ __forceinline__ void scan2304(float* buf, int tx) {
    __shared__ float wtot[8];
    float v[9];
    float run = 0.f;
    int base = tx * 9;
#pragma unroll
    for (int k = 0; k < 9; ++k) { run += buf[base + k]; v[k] = run; }
    float t = run;
    int lane = tx & 31;
#pragma unroll
    for (int off = 1; off < 32; off <<= 1) {
        float n = __shfl_up_sync(0xffffffffu, t, off);
        if (lane >= off) t += n;
    }
    if (lane == 31) wtot[tx >> 5] = t;
    __syncthreads();
    if (tx < 8) {
        float w = wtot[tx];
#pragma unroll
        for (int off = 1; off < 8; off <<= 1) {
            float n = __shfl_up_sync(0xffu, w, off);
            if (tx >= off) w += n;
        }
        wtot[tx] = w;
    }
    __syncthreads();
    float offv = (t - run) + ((tx >= 32) ? wtot[(tx >> 5) - 1] : 0.f);
#pragma unroll
    for (int k = 0; k < 9; ++k) buf[base + k] = v[k] + offv;
    __syncthreads();
}

// Load one row of a plane into shifted buffer: buf[0]=0, buf[1+j]=row[j-RAD] (0 OOB)
__device__ __forceinline__ void load_row(float* buf, const float* __restrict__ plane,
                                         int row, int tx) {
    const float* p = plane + row * WW;
    for (int idx = tx; idx < 2304; idx += 256) {
        int j = idx - 1;
        unsigned x = (unsigned)(j - RAD);
        buf[idx] = (idx > 0 && x < (unsigned)WW) ? p[x] : 0.f;
    }
}

// ---------------------------------------------------------------------------
// K2: horizontal box of the 3 vertical planes via prefix sums, then the
// 8-channel global reductions (c0 num/den, num[3], den[3]). One block per row.
// ---------------------------------------------------------------------------
__global__ void k2_hor_red(const float* __restrict__ I, const float* __restrict__ e,
                           const float* __restrict__ u) {
    __shared__ float buf0[2304], buf1[2304], buf2[2304];
    __shared__ float sred[64];
    int tx = threadIdx.x;
    int row = blockIdx.x;

    load_row(buf0, g_P0, row, tx);
    load_row(buf1, g_P1, row, tx);
    load_row(buf2, g_P2, row, tx);
    __syncthreads();
    scan2304(buf0, tx);
    scan2304(buf1, tx);
    scan2304(buf2, tx);

    float a0 = 0, a1 = 0, a2 = 0, a3 = 0, a4 = 0, a5 = 0, a6 = 0, a7 = 0;
    int rowoff = row * WW;
#pragma unroll
    for (int i = 0; i < 8; ++i) {
        int x = tx + 256 * i;
        int o = rowoff + x;
        float norm = buf0[x + 21] - buf0[x];
        float inv = 1.f / (norm + EPSF);
        float bK  = (buf1[x + 21] - buf1[x]) * inv;
        float b2K = (buf2[x + 21] - buf2[x]) * inv;
        float Iv = I[o], ev = e[o];
        float u0 = u[o], u1v = u[HWN + o], u2v = u[2 * HWN + o], u3v = u[3 * HWN + o];
        float p0 = u0 * u0, p1 = u1v * u1v, p2 = u2v * u2v, p3 = u3v * u3v;
        float A = (Iv - ev) * bK;
        a0 += Iv * p0;  a1 += p0;
        a2 += A * p1;   a3 += A * p2;   a4 += A * p3;
        a5 += b2K * p1; a6 += b2K * p2; a7 += b2K * p3;
    }
    float ch[8] = {a0, a1, a2, a3, a4, a5, a6, a7};
    int lane = tx & 31, w = tx >> 5;
#pragma unroll
    for (int c = 0; c < 8; ++c) {
        float v = ch[c];
#pragma unroll
        for (int off = 16; off; off >>= 1) v += __shfl_down_sync(0xffffffffu, v, off);
        if (lane == 0) sred[w * 8 + c] = v;
    }
    __syncthreads();
    if (tx < 8) {
        double s = 0;
#pragma unroll
        for (int ww2 = 0; ww2 < 8; ++ww2) s += (double)sred[ww2 * 8 + tx];
        g_red[row * 8 + tx] = s;
    }
}

// ---------------------------------------------------------------------------
// K3: single-block final reduction -> v[4]
// channels: 0: sum(I*up0) 1: sum(up0) 2-4: num[1..3] 5-7: den[1..3]
// ---------------------------------------------------------------------------
__global__ void k3_v() {
    __shared__ double sm[256];
    __shared__ double tot[8];
    int tx = threadIdx.x;
    double acc[8] = {0, 0, 0, 0, 0, 0, 0, 0};
    for (int i = tx; i < HH; i += 256)
#pragma unroll
        for (int c = 0; c < 8; ++c) acc[c] += g_red[i * 8 + c];
    for (int c = 0; c < 8; ++c) {
        sm[tx] = acc[c];
        __syncthreads();
        for (int s = 128; s > 0; s >>= 1) {
            if (tx < s) sm[tx] += sm[tx + s];
            __syncthreads();
        }
        if (tx == 0) tot[c] = sm[0];
        __syncthreads();
    }
    if (tx == 0) {
        g_v[0] = (float)(tot[0] / (tot[1] + 1e-9));
        g_v[1] = (float)(tot[2] / (tot[5] + 1e-9));
        g_v[2] = (float)(tot[3] / (tot[6] + 1e-9));
        g_v[3] = (float)(tot[4] / (tot[7] + 1e-9));
    }
}

// ---------------------------------------------------------------------------
// K4: vertical box of S1=(I-e)*sum(v*up), S2=sum(v^2*up) -> g_P1, g_P2
// ---------------------------------------------------------------------------
__device__ __forceinline__ float2 compS(const float* __restrict__ I,
                                        const float* __restrict__ e,
                                        const float* __restrict__ u, int o,
                                        float v0, float v1, float v2, float v3,
                                        float w0, float w1, float w2, float w3) {
    float u0 = u[o], u1 = u[HWN + o], u2 = u[2 * HWN + o], u3 = u[3 * HWN + o];
    float p0 = u0 * u0, p1 = u1 * u1, p2 = u2 * u2, p3 = u3 * u3;
    float sv = v0 * p0 + v1 * p1 + v2 * p2 + v3 * p3;
    float sw = w0 * p0 + w1 * p1 + w2 * p2 + w3 * p3;
    return make_float2((I[o] - e[o]) * sv, sw);
}

__global__ void k4_vert(const float* __restrict__ I, const float* __restrict__ e,
                        const float* __restrict__ u) {
    int col = blockIdx.x * 256 + threadIdx.x;
    int r0 = blockIdx.y * SEG;
    float v0 = g_v[0], v1 = g_v[1], v2 = g_v[2], v3 = g_v[3];
    float w0 = v0 * v0, w1 = v1 * v1, w2 = v2 * v2, w3 = v3 * v3;
    float s1 = 0.f, s2 = 0.f;
    for (int y = r0 - RAD; y <= r0 + RAD; ++y) {
        if (y >= 0 && y < HH) {
            float2 s = compS(I, e, u, y * WW + col, v0, v1, v2, v3, w0, w1, w2, w3);
            s1 += s.x; s2 += s.y;
        }
    }
    for (int i = 0; i < SEG; ++i) {
        int y = r0 + i;
        int o = y * WW + col;
        g_P1[o] = s1; g_P2[o] = s2;
        int ya = y + RAD + 1, yr = y - RAD;
        if (ya < HH) {
            float2 s = compS(I, e, u, ya * WW + col, v0, v1, v2, v3, w0, w1, w2, w3);
            s1 += s.x; s2 += s.y;
        }
        if (yr >= 0) {
            float2 s = compS(I, e, u, yr * WW + col, v0, v1, v2, v3, w0, w1, w2, w3);
            s1 -= s.x; s2 -= s.y;
        }
    }
}

// ---------------------------------------------------------------------------
// K5: horizontal box of {norm(=P0), S1, S2}; masked combine; loss partials
// ---------------------------------------------------------------------------
__global__ void k5_hor_fin(const float* __restrict__ I, const float* __restrict__ B) {
    __shared__ float buf0[2304], buf1[2304], buf2[2304];
    __shared__ double sw[8];
    int tx = threadIdx.x;
    int row = blockIdx.x;

    load_row(buf0, g_P0, row, tx);
    load_row(buf1, g_P1, row, tx);
    load_row(buf2, g_P2, row, tx);
    __syncthreads();
    scan2304(buf0, tx);
    scan2304(buf1, tx);
    scan2304(buf2, tx);

    float acc = 0.f;
    int rowoff = row * WW;
#pragma unroll
    for (int i = 0; i < 8; ++i) {
        int x = tx + 256 * i;
        int o = rowoff + x;
        float norm = buf0[x + 21] - buf0[x];
        float inv = 1.f / (norm + EPSF);
        float bd = (buf1[x + 21] - buf1[x]) * inv;
        float db = (buf2[x + 21] - buf2[x]) * inv;
        float Iv = I[o];
        float m = (Iv > THR) ? 1.f : 0.f;
        bd = bd * m + (1.f - m);
        db = db * m + (1.f - m);
        float bn = bd / (db + EPSF);
        float d = B[o] - bn;
        acc += d * d;
    }
    int lane = tx & 31, w = tx >> 5;
#pragma unroll
    for (int off = 16; off; off >>= 1) acc += __shfl_down_sync(0xffffffffu, acc, off);
    if (lane == 0) sw[w] = (double)acc;
    __syncthreads();
    if (tx == 0) {
        double s = 0;
#pragma unroll
        for (int ww2 = 0; ww2 < 8; ++ww2) s += sw[ww2];
        g_red2[row] = s;
    }
}

// ---------------------------------------------------------------------------
// K6: final scalar = mean(diff^2)
// ---------------------------------------------------------------------------
__global__ void k6_out(float* __restrict__ out) {
    __shared__ double sm[256];
    int tx = threadIdx.x;
    double a = 0;
    for (int i = tx; i < HH; i += 256) a += g_red2[i];
    sm[tx] = a;
    __syncthreads();
    for (int s = 128; s > 0; s >>= 1) {
        if (tx < s) sm[tx] += sm[tx + s];
        __syncthreads();
    }
    if (tx == 0) out[0] = (float)(sm[0] / (double)HWN);
}

// ---------------------------------------------------------------------------
extern "C" void kernel_launch(void* const* d_in, const int* in_sizes, int n_in,
                              void* d_out, int out_size) {
    (void)in_sizes; (void)n_in; (void)out_size;
    const float* I = (const float*)d_in[0];
    const float* u = (const float*)d_in[1];
    const float* b = (const float*)d_in[2];
    const float* e = (const float*)d_in[3];
    // p=2, size=21 are fixed by the problem setup.

    dim3 bv(256);
    dim3 gv(WW / 256, HH / SEG);

    k1_vert<<<gv, bv>>>(I, b);
    k2_hor_red<<<HH, 256>>>(I, e, u);
    k3_v<<<1, 256>>>();
    k4_vert<<<gv, bv>>>(I, e, u);
    k5_hor_fin<<<HH, 256>>>(I, b);
    k6_out<<<1, 256>>>((float*)d_out);
}

// round 2
// speedup vs baseline: 1.7721x; 1.7721x over previous
#include <cuda_runtime.h>

#define HH 2048
#define WW 2048
#define W4 (WW/4)
#define HWN (HH*WW)
#define HWN4 (HWN/4)
#define RAD 10
#define SEG 16
#define THR 1e-3f
#define EPSF 1e-9f

// Scratch planes (device globals: no allocation allowed)
__device__ float g_P0[HWN];        // vertical box of mask (persists K1 -> K5)
__device__ float g_P1[HWN];        // vertical box of b, later of S1
__device__ float g_P2[HWN];        // vertical box of b*b, later of S2
__device__ float g_S1[HWN];        // elementwise S1 field
__device__ float g_S2[HWN];        // elementwise S2 field
__device__ double g_red[HH * 8];   // per-row partial reductions (8 channels)
__device__ double g_red2[HH];      // per-row partial loss sums
__device__ float g_v[4];           // the 4-vector v

// ---- float4 helpers --------------------------------------------------------
__device__ __forceinline__ float4 f4z() { return make_float4(0.f, 0.f, 0.f, 0.f); }
__device__ __forceinline__ float4 f4add(float4 a, float4 b) {
    return make_float4(a.x + b.x, a.y + b.y, a.z + b.z, a.w + b.w);
}
__device__ __forceinline__ float4 f4sub(float4 a, float4 b) {
    return make_float4(a.x - b.x, a.y - b.y, a.z - b.z, a.w - b.w);
}
__device__ __forceinline__ float4 f4mul(float4 a, float4 b) {
    return make_float4(a.x * b.x, a.y * b.y, a.z * b.z, a.w * b.w);
}
__device__ __forceinline__ float4 f4mask(float4 i) {
    return make_float4(i.x > THR ? 1.f : 0.f, i.y > THR ? 1.f : 0.f,
                       i.z > THR ? 1.f : 0.f, i.w > THR ? 1.f : 0.f);
}

// ---------------------------------------------------------------------------
// K1: vertical 21-tap box sums of {mask(I), b, b*b}, float4 sliding window
// grid (W4/256, HH/SEG), block 256
// ---------------------------------------------------------------------------
__global__ void k1_vert(const float4* __restrict__ I4, const float4* __restrict__ B4) {
    int col = blockIdx.x * 256 + threadIdx.x;
    int r0 = blockIdx.y * SEG;
    float4 s0 = f4z(), s1 = f4z(), s2 = f4z();
    for (int y = r0 - RAD; y <= r0 + RAD; ++y) {
        if (y >= 0 && y < HH) {
            float4 iv = __ldg(I4 + y * W4 + col);
            float4 bv = __ldg(B4 + y * W4 + col);
            s0 = f4add(s0, f4mask(iv));
            s1 = f4add(s1, bv);
            s2 = f4add(s2, f4mul(bv, bv));
        }
    }
    float4* P0 = (float4*)g_P0;
    float4* P1 = (float4*)g_P1;
    float4* P2 = (float4*)g_P2;
#pragma unroll 4
    for (int i = 0; i < SEG; ++i) {
        int y = r0 + i;
        int ya = y + RAD + 1, yr = y - RAD;
        float4 ia = f4z(), ba = f4z(), ir = f4z(), br = f4z();
        if (ya < HH) { ia = __ldg(I4 + ya * W4 + col); ba = __ldg(B4 + ya * W4 + col); }
        if (yr >= 0) { ir = __ldg(I4 + yr * W4 + col); br = __ldg(B4 + yr * W4 + col); }
        int o = y * W4 + col;
        P0[o] = s0; P1[o] = s1; P2[o] = s2;
        s0 = f4add(s0, f4sub(f4mask(ia), f4mask(ir)));
        s1 = f4add(s1, f4sub(ba, br));
        s2 = f4add(s2, f4sub(f4mul(ba, ba), f4mul(br, br)));
    }
}

// ---------------------------------------------------------------------------
// Block-wide inclusive prefix sum of 2304 floats in shared memory (256 thr).
// Stride-9 per-thread segments => conflict-free (gcd(9,32)=1).
// ---------------------------------------------------------------------------
__device__ __forceinline__ void scan2304(float* buf, int tx) {
    __shared__ float wtot[8];
    float v[9];
    float run = 0.f;
    int base = tx * 9;
#pragma unroll
    for (int k = 0; k < 9; ++k) { run += buf[base + k]; v[k] = run; }
    float t = run;
    int lane = tx & 31;
#pragma unroll
    for (int off = 1; off < 32; off <<= 1) {
        float n = __shfl_up_sync(0xffffffffu, t, off);
        if (lane >= off) t += n;
    }
    if (lane == 31) wtot[tx >> 5] = t;
    __syncthreads();
    if (tx < 8) {
        float w = wtot[tx];
#pragma unroll
        for (int off = 1; off < 8; off <<= 1) {
            float n = __shfl_up_sync(0xffu, w, off);
            if (tx >= off) w += n;
        }
        wtot[tx] = w;
    }
    __syncthreads();
    float offv = (t - run) + ((tx >= 32) ? wtot[(tx >> 5) - 1] : 0.f);
#pragma unroll
    for (int k = 0; k < 9; ++k) buf[base + k] = v[k] + offv;
    __syncthreads();
}

// Load one row into shifted buffer via float4: buf[k] = row[k-11] (0 OOB), buf[0..10]=0
__device__ __forceinline__ void load_row4(float* buf, const float* __restrict__ plane,
                                          int row, int tx) {
    const float4* p4 = (const float4*)(plane + row * WW);
#pragma unroll
    for (int t = tx; t < 512; t += 256) {
        float4 v = __ldg(p4 + t);
        int i = 4 * t + 11;
        buf[i] = v.x; buf[i + 1] = v.y; buf[i + 2] = v.z; buf[i + 3] = v.w;
    }
    if (tx < 11) buf[tx] = 0.f;
    if (tx < 245) buf[2059 + tx] = 0.f;
}

// ---------------------------------------------------------------------------
// K2: horizontal box of 3 vertical planes via prefix sums + 8-channel reductions
// ---------------------------------------------------------------------------
__global__ void k2_hor_red(const float4* __restrict__ I4, const float4* __restrict__ e4,
                           const float4* __restrict__ u4) {
    __shared__ float buf0[2304], buf1[2304], buf2[2304];
    __shared__ float sred[64];
    int tx = threadIdx.x;
    int row = blockIdx.x;

    load_row4(buf0, g_P0, row, tx);
    load_row4(buf1, g_P1, row, tx);
    load_row4(buf2, g_P2, row, tx);
    __syncthreads();
    scan2304(buf0, tx);
    scan2304(buf1, tx);
    scan2304(buf2, tx);

    float a[8] = {0, 0, 0, 0, 0, 0, 0, 0};
    int row4 = row * W4;
#pragma unroll
    for (int i = 0; i < 2; ++i) {
        int x4 = tx + 256 * i;
        int o = row4 + x4;
        float4 Iv = __ldg(I4 + o), ev = __ldg(e4 + o);
        float4 U0 = __ldg(u4 + o), U1 = __ldg(u4 + HWN4 + o);
        float4 U2 = __ldg(u4 + 2 * HWN4 + o), U3 = __ldg(u4 + 3 * HWN4 + o);
        const float* fI = (const float*)&Iv;
        const float* fe = (const float*)&ev;
        const float* f0 = (const float*)&U0;
        const float* f1 = (const float*)&U1;
        const float* f2 = (const float*)&U2;
        const float* f3 = (const float*)&U3;
        int p = 4 * x4;
#pragma unroll
        for (int c = 0; c < 4; ++c) {
            float norm = buf0[p + c + 21] - buf0[p + c];
            float inv = 1.f / (norm + EPSF);
            float bK  = (buf1[p + c + 21] - buf1[p + c]) * inv;
            float b2K = (buf2[p + c + 21] - buf2[p + c]) * inv;
            float p0 = f0[c] * f0[c], p1 = f1[c] * f1[c];
            float p2 = f2[c] * f2[c], p3 = f3[c] * f3[c];
            float A = (fI[c] - fe[c]) * bK;
            a[0] += fI[c] * p0; a[1] += p0;
            a[2] += A * p1;  a[3] += A * p2;  a[4] += A * p3;
            a[5] += b2K * p1; a[6] += b2K * p2; a[7] += b2K * p3;
        }
    }
    int lane = tx & 31, w = tx >> 5;
#pragma unroll
    for (int c = 0; c < 8; ++c) {
        float v = a[c];
#pragma unroll
        for (int off = 16; off; off >>= 1) v += __shfl_down_sync(0xffffffffu, v, off);
        if (lane == 0) sred[w * 8 + c] = v;
    }
    __syncthreads();
    if (tx < 8) {
        double s = 0;
#pragma unroll
        for (int ww2 = 0; ww2 < 8; ++ww2) s += (double)sred[ww2 * 8 + tx];
        g_red[row * 8 + tx] = s;
    }
}

// ---------------------------------------------------------------------------
// K3: single-block final reduction -> v[4]
// ---------------------------------------------------------------------------
__global__ void k3_v() {
    __shared__ double sm[256];
    __shared__ double tot[8];
    int tx = threadIdx.x;
    double acc[8] = {0, 0, 0, 0, 0, 0, 0, 0};
    for (int i = tx; i < HH; i += 256)
#pragma unroll
        for (int c = 0; c < 8; ++c) acc[c] += g_red[i * 8 + c];
    for (int c = 0; c < 8; ++c) {
        sm[tx] = acc[c];
        __syncthreads();
        for (int s = 128; s > 0; s >>= 1) {
            if (tx < s) sm[tx] += sm[tx + s];
            __syncthreads();
        }
        if (tx == 0) tot[c] = sm[0];
        __syncthreads();
    }
    if (tx == 0) {
        g_v[0] = (float)(tot[0] / (tot[1] + 1e-9));
        g_v[1] = (float)(tot[2] / (tot[5] + 1e-9));
        g_v[2] = (float)(tot[3] / (tot[6] + 1e-9));
        g_v[3] = (float)(tot[4] / (tot[7] + 1e-9));
    }
}

// ---------------------------------------------------------------------------
// K4a: elementwise S1=(I-e)*sum(v*up), S2=sum(v^2*up) — pure streaming, float4
// ---------------------------------------------------------------------------
__global__ void k4a_elem(const float4* __restrict__ I4, const float4* __restrict__ e4,
                         const float4* __restrict__ u4) {
    int idx = blockIdx.x * 256 + threadIdx.x;
    float v0 = g_v[0], v1 = g_v[1], v2 = g_v[2], v3 = g_v[3];
    float w0 = v0 * v0, w1 = v1 * v1, w2 = v2 * v2, w3 = v3 * v3;
    float4 Iv = __ldg(I4 + idx), ev = __ldg(e4 + idx);
    float4 U0 = __ldg(u4 + idx), U1 = __ldg(u4 + HWN4 + idx);
    float4 U2 = __ldg(u4 + 2 * HWN4 + idx), U3 = __ldg(u4 + 3 * HWN4 + idx);
    float4 P0 = f4mul(U0, U0), P1 = f4mul(U1, U1);
    float4 P2 = f4mul(U2, U2), P3 = f4mul(U3, U3);
    float4 s1, s2;
    s1.x = (Iv.x - ev.x) * (v0 * P0.x + v1 * P1.x + v2 * P2.x + v3 * P3.x);
    s1.y = (Iv.y - ev.y) * (v0 * P0.y + v1 * P1.y + v2 * P2.y + v3 * P3.y);
    s1.z = (Iv.z - ev.z) * (v0 * P0.z + v1 * P1.z + v2 * P2.z + v3 * P3.z);
    s1.w = (Iv.w - ev.w) * (v0 * P0.w + v1 * P1.w + v2 * P2.w + v3 * P3.w);
    s2.x = w0 * P0.x + w1 * P1.x + w2 * P2.x + w3 * P3.x;
    s2.y = w0 * P0.y + w1 * P1.y + w2 * P2.y + w3 * P3.y;
    s2.z = w0 * P0.z + w1 * P1.z + w2 * P2.z + w3 * P3.z;
    s2.w = w0 * P0.w + w1 * P1.w + w2 * P2.w + w3 * P3.w;
    ((float4*)g_S1)[idx] = s1;
    ((float4*)g_S2)[idx] = s2;
}

// ---------------------------------------------------------------------------
// K4b: vertical box of S1,S2 -> g_P1,g_P2 (float4 sliding window)
// ---------------------------------------------------------------------------
__global__ void k4b_vert() {
    int col = blockIdx.x * 256 + threadIdx.x;
    int r0 = blockIdx.y * SEG;
    const float4* S1 = (const float4*)g_S1;
    const float4* S2 = (const float4*)g_S2;
    float4* P1 = (float4*)g_P1;
    float4* P2 = (float4*)g_P2;
    float4 s1 = f4z(), s2 = f4z();
    for (int y = r0 - RAD; y <= r0 + RAD; ++y) {
        if (y >= 0 && y < HH) {
            s1 = f4add(s1, __ldg(S1 + y * W4 + col));
            s2 = f4add(s2, __ldg(S2 + y * W4 + col));
        }
    }
#pragma unroll 4
    for (int i = 0; i < SEG; ++i) {
        int y = r0 + i;
        int ya = y + RAD + 1, yr = y - RAD;
        float4 aa = f4z(), ab = f4z(), ra = f4z(), rb = f4z();
        if (ya < HH) { aa = __ldg(S1 + ya * W4 + col); ab = __ldg(S2 + ya * W4 + col); }
        if (yr >= 0) { ra = __ldg(S1 + yr * W4 + col); rb = __ldg(S2 + yr * W4 + col); }
        int o = y * W4 + col;
        P1[o] = s1; P2[o] = s2;
        s1 = f4add(s1, f4sub(aa, ra));
        s2 = f4add(s2, f4sub(ab, rb));
    }
}

// ---------------------------------------------------------------------------
// K5: horizontal box of {norm(=P0), S1v, S2v}; masked combine; loss partials
// ---------------------------------------------------------------------------
__global__ void k5_hor_fin(const float4* __restrict__ I4, const float4* __restrict__ B4) {
    __shared__ float buf0[2304], buf1[2304], buf2[2304];
    __shared__ double sw[8];
    int tx = threadIdx.x;
    int row = blockIdx.x;

    load_row4(buf0, g_P0, row, tx);
    load_row4(buf1, g_P1, row, tx);
    load_row4(buf2, g_P2, row, tx);
    __syncthreads();
    scan2304(buf0, tx);
    scan2304(buf1, tx);
    scan2304(buf2, tx);

    float acc = 0.f;
    int row4 = row * W4;
#pragma unroll
    for (int i = 0; i < 2; ++i) {
        int x4 = tx + 256 * i;
        int o = row4 + x4;
        float4 Iv = __ldg(I4 + o), Bv = __ldg(B4 + o);
        const float* fI = (const float*)&Iv;
        const float* fB = (const float*)&Bv;
        int p = 4 * x4;
#pragma unroll
        for (int c = 0; c < 4; ++c) {
            float norm = buf0[p + c + 21] - buf0[p + c];
            float inv = 1.f / (norm + EPSF);
            float bd = (buf1[p + c + 21] - buf1[p + c]) * inv;
            float db = (buf2[p + c + 21] - buf2[p + c]) * inv;
            float m = (fI[c] > THR) ? 1.f : 0.f;
            bd = bd * m + (1.f - m);
            db = db * m + (1.f - m);
            float bn = bd / (db + EPSF);
            float d = fB[c] - bn;
            acc += d * d;
        }
    }
    int lane = tx & 31, w = tx >> 5;
#pragma unroll
    for (int off = 16; off; off >>= 1) acc += __shfl_down_sync(0xffffffffu, acc, off);
    if (lane == 0) sw[w] = (double)acc;
    __syncthreads();
    if (tx == 0) {
        double s = 0;
#pragma unroll
        for (int ww2 = 0; ww2 < 8; ++ww2) s += sw[ww2];
        g_red2[row] = s;
    }
}

// ---------------------------------------------------------------------------
// K6: final scalar = mean(diff^2)
// ---------------------------------------------------------------------------
__global__ void k6_out(float* __restrict__ out) {
    __shared__ double sm[256];
    int tx = threadIdx.x;
    double a = 0;
    for (int i = tx; i < HH; i += 256) a += g_red2[i];
    sm[tx] = a;
    __syncthreads();
    for (int s = 128; s > 0; s >>= 1) {
        if (tx < s) sm[tx] += sm[tx + s];
        __syncthreads();
    }
    if (tx == 0) out[0] = (float)(sm[0] / (double)HWN);
}

// ---------------------------------------------------------------------------
extern "C" void kernel_launch(void* const* d_in, const int* in_sizes, int n_in,
                              void* d_out, int out_size) {
    (void)in_sizes; (void)n_in; (void)out_size;
    const float4* I = (const float4*)d_in[0];
    const float4* u = (const float4*)d_in[1];
    const float4* b = (const float4*)d_in[2];
    const float4* e = (const float4*)d_in[3];

    dim3 gv(W4 / 256, HH / SEG);

    k1_vert<<<gv, 256>>>(I, b);
    k2_hor_red<<<HH, 256>>>(I, e, u);
    k3_v<<<1, 256>>>();
    k4a_elem<<<HWN4 / 256, 256>>>(I, e, u);
    k4b_vert<<<gv, 256>>>();
    k5_hor_fin<<<HH, 256>>>(I, b);
    k6_out<<<1, 256>>>((float*)d_out);
}